// round 16
// baseline (speedup 1.0000x reference)
#include <cuda_runtime.h>
#include <cuda_bf16.h>
#include <math.h>
#include <stdint.h>

#define DD 256
#define SS 256
#define NB 64

// Scratch (device globals; no allocation allowed)
__device__ float d_L[(size_t)SS * DD * DD];                 // 64 MB: Sigma -> L (lower valid)
__device__ float d_invDiag[(size_t)SS * 4 * NB * NB];       // inv of diag 64x64 blocks
__device__ __nv_bfloat16 d_LinvH[(size_t)SS * DD * DD];     // 32 MB: hi plane of L^-1
__device__ __nv_bfloat16 d_LinvL[(size_t)SS * DD * DD];     // 32 MB: lo plane of L^-1
__device__ __nv_bfloat16 d_xH[(size_t)1024 * DD];           // x hi plane
__device__ __nv_bfloat16 d_xL[(size_t)1024 * DD];           // x lo plane
__device__ float d_w[(size_t)SS * DD];                      // w = Linv * mu
__device__ float d_ridge[SS];
__device__ float d_logdet[SS];

// ======================= PTX helpers (sm_80-level only) =======================
__device__ __forceinline__ uint32_t smem_u32(const void* p) {
    uint32_t a;
    asm("{ .reg .u64 t; cvta.to.shared.u64 t, %1; cvt.u32.u64 %0, t; }" : "=r"(a) : "l"(p));
    return a;
}
__device__ __forceinline__ void ldsm_x4(uint32_t& r0, uint32_t& r1, uint32_t& r2, uint32_t& r3,
                                        uint32_t addr) {
    asm volatile("ldmatrix.sync.aligned.m8n8.x4.shared.b16 {%0,%1,%2,%3}, [%4];"
                 : "=r"(r0), "=r"(r1), "=r"(r2), "=r"(r3) : "r"(addr));
}
__device__ __forceinline__ void ldsm_x4t(uint32_t& r0, uint32_t& r1, uint32_t& r2, uint32_t& r3,
                                         uint32_t addr) {
    asm volatile("ldmatrix.sync.aligned.m8n8.x4.trans.shared.b16 {%0,%1,%2,%3}, [%4];"
                 : "=r"(r0), "=r"(r1), "=r"(r2), "=r"(r3) : "r"(addr));
}
__device__ __forceinline__ void mma_bf16(float* d, const uint32_t* a, uint32_t b0, uint32_t b1) {
    asm volatile("mma.sync.aligned.m16n8k16.row.col.f32.bf16.bf16.f32 "
                 "{%0,%1,%2,%3}, {%4,%5,%6,%7}, {%8,%9}, {%0,%1,%2,%3};"
                 : "+f"(d[0]), "+f"(d[1]), "+f"(d[2]), "+f"(d[3])
                 : "r"(a[0]), "r"(a[1]), "r"(a[2]), "r"(a[3]), "r"(b0), "r"(b1));
}
__device__ __forceinline__ void cvt_split(float4 v, uint2& hi, uint2& lo) {
    __nv_bfloat16 h0 = __float2bfloat16(v.x), h1 = __float2bfloat16(v.y),
                  h2 = __float2bfloat16(v.z), h3 = __float2bfloat16(v.w);
    __nv_bfloat16 l0 = __float2bfloat16(v.x - __bfloat162float(h0));
    __nv_bfloat16 l1 = __float2bfloat16(v.y - __bfloat162float(h1));
    __nv_bfloat16 l2 = __float2bfloat16(v.z - __bfloat162float(h2));
    __nv_bfloat16 l3 = __float2bfloat16(v.w - __bfloat162float(h3));
    __nv_bfloat162 ph0 = __halves2bfloat162(h0, h1), ph1 = __halves2bfloat162(h2, h3);
    __nv_bfloat162 pl0 = __halves2bfloat162(l0, l1), pl1 = __halves2bfloat162(l2, l3);
    hi.x = *(uint32_t*)&ph0; hi.y = *(uint32_t*)&ph1;
    lo.x = *(uint32_t*)&pl0; lo.y = *(uint32_t*)&pl1;
}
#define CP_ASYNC16(dst, src) \
    asm volatile("cp.async.cg.shared.global [%0], [%1], 16;" :: "r"(dst), "l"(src))

// ---------------------------------------------------------------------------
// Kernel 1: ridge[s] = 0.01 * ||sp_s||_F^2 / D
// ---------------------------------------------------------------------------
__global__ __launch_bounds__(256) void ridge_kernel(const float* __restrict__ sp) {
    const int s = blockIdx.x;
    const float* A = sp + (size_t)s * DD * DD;
    float acc = 0.f;
    for (int i = threadIdx.x; i < DD * DD; i += 256) { float v = A[i]; acc += v * v; }
    __shared__ float red[256];
    red[threadIdx.x] = acc; __syncthreads();
    for (int o = 128; o > 0; o >>= 1) {
        if (threadIdx.x < o) red[threadIdx.x] += red[threadIdx.x + o];
        __syncthreads();
    }
    if (threadIdx.x == 0) d_ridge[s] = 0.01f * red[0] / (float)DD;
}

// ---------------------------------------------------------------------------
// Kernel 1b: x -> bf16 hi/lo planes
// ---------------------------------------------------------------------------
__global__ __launch_bounds__(256) void xcvt_kernel(const float* __restrict__ x) {
    int idx = blockIdx.x * 256 + threadIdx.x;        // 65536 float4s
    float4 v = ((const float4*)x)[idx];
    uint2 hi, lo; cvt_split(v, hi, lo);
    ((uint2*)d_xH)[idx] = hi;
    ((uint2*)d_xL)[idx] = lo;
}

// ---------------------------------------------------------------------------
// Kernel 2: Sigma_s = sp^T sp + ridge*I via mma.sync bf16-split.
// ---------------------------------------------------------------------------
#define SLDK 264
__global__ __launch_bounds__(256) void syrk_kernel(const float* __restrict__ sp) {
    extern __shared__ __nv_bfloat16 smh[];
    const uint32_t sbase = smem_u32(smh);
    const uint32_t LO = 64 * SLDK;
    const int t = blockIdx.x;
    const int ti = (t + 1) >> 1, tj = t >> 1;   // (0,0),(1,0),(1,1)
    const int s = blockIdx.y;
    const float* A = sp + (size_t)s * DD * DD;
    float* C = d_L + (size_t)s * DD * DD;

    const int tid = threadIdx.x, wid = tid >> 5, lane = tid & 31;
    const int wm = wid & 3, wn = wid >> 2;
    const int dlo = (ti == tj) ? ti * 128 : 0;
    const int dw  = (ti == tj) ? 128 : 256;
    const int gm0 = ti * 128 + wm * 32, gn0 = tj * 128 + wn * 64;
    const int lm0 = gm0 - dlo, ln0 = gn0 - dlo;

    const int lt = lane >> 3, lr = lane & 7;
    const uint32_t aK = lr + 8 * (lt >> 1), aM = 8 * (lt & 1);
    const uint32_t bK = lr + 8 * (lt & 1),  bN = 8 * (lt >> 1);

    float acc[2][8][4];
#pragma unroll
    for (int i = 0; i < 2; i++)
#pragma unroll
        for (int j = 0; j < 8; j++)
#pragma unroll
            for (int r = 0; r < 4; r++) acc[i][j][r] = 0.f;

    for (int k0 = 0; k0 < DD; k0 += 64) {
        for (int idx = tid; idx < 16 * dw; idx += 256) {
            int k = idx / (dw >> 2), dq = (idx % (dw >> 2)) << 2;
            float4 v = *(const float4*)(A + (size_t)(k0 + k) * DD + dlo + dq);
            uint2 hi, lo; cvt_split(v, hi, lo);
            *(uint2*)(smh + k * SLDK + dq) = hi;
            *(uint2*)(smh + LO + k * SLDK + dq) = lo;
        }
        __syncthreads();
#pragma unroll
        for (int ks = 0; ks < 4; ks++) {
            const uint32_t kc = ks * 16;
            uint32_t ahi[2][4], alo[2][4];
#pragma unroll
            for (int i = 0; i < 2; i++) {
                uint32_t ra = (kc + aK) * SLDK + lm0 + i * 16 + aM;
                ldsm_x4t(ahi[i][0], ahi[i][1], ahi[i][2], ahi[i][3], sbase + ra * 2);
                ldsm_x4t(alo[i][0], alo[i][1], alo[i][2], alo[i][3], sbase + (LO + ra) * 2);
            }
#pragma unroll
            for (int p = 0; p < 4; p++) {
                uint32_t bhi[4], blo[4];
                uint32_t rb = (kc + bK) * SLDK + ln0 + p * 16 + bN;
                ldsm_x4t(bhi[0], bhi[1], bhi[2], bhi[3], sbase + rb * 2);
                ldsm_x4t(blo[0], blo[1], blo[2], blo[3], sbase + (LO + rb) * 2);
#pragma unroll
                for (int i = 0; i < 2; i++) {
                    mma_bf16(acc[i][2 * p + 0], ahi[i], bhi[0], bhi[1]);
                    mma_bf16(acc[i][2 * p + 1], ahi[i], bhi[2], bhi[3]);
                    mma_bf16(acc[i][2 * p + 0], ahi[i], blo[0], blo[1]);
                    mma_bf16(acc[i][2 * p + 1], ahi[i], blo[2], blo[3]);
                    mma_bf16(acc[i][2 * p + 0], alo[i], bhi[0], bhi[1]);
                    mma_bf16(acc[i][2 * p + 1], alo[i], bhi[2], bhi[3]);
                }
            }
        }
        __syncthreads();
    }

    const float ridge = d_ridge[s];
    const int crow = lane >> 2, ccol = 2 * (lane & 3);
#pragma unroll
    for (int i = 0; i < 2; i++)
#pragma unroll
        for (int j = 0; j < 8; j++) {
            int row = gm0 + i * 16 + crow;
            int col = gn0 + j * 8 + ccol;
            float c0 = acc[i][j][0], c1 = acc[i][j][1], c2 = acc[i][j][2], c3 = acc[i][j][3];
            if (row == col) c0 += ridge;
            if (row == col + 1) c1 += ridge;
            if (row + 8 == col) c2 += ridge;
            if (row + 8 == col + 1) c3 += ridge;
            *(float2*)&C[(size_t)row * DD + col] = make_float2(c0, c1);
            *(float2*)&C[(size_t)(row + 8) * DD + col] = make_float2(c2, c3);
        }
}

// ---------------------------------------------------------------------------
// Kernel 3: per-s blocked Cholesky (serial only on 64x64 diag; L21 via GEMM).
// smem = (256*65 + 64*68)*4 = 83968 B.
// ---------------------------------------------------------------------------
__global__ __launch_bounds__(256) void chol_kernel() {
    extern __shared__ float sm[];
    float* sP = sm;               // 256*65 panel
    float* sI = sm + 256 * 65;    // 64*68 invD
    __shared__ float sLd;
    const int s = blockIdx.x;
    const int tid = threadIdx.x;
    const int tx = tid & 15, ty = tid >> 4;
    float* L = d_L + (size_t)s * DD * DD;
    if (tid == 0) sLd = 0.f;

    for (int p = 0; p < 4; p++) {
        const int r0 = p * NB;
        const int nrows = DD - r0;
        for (int idx = tid; idx < nrows * NB; idx += 256)
            sP[(idx >> 6) * 65 + (idx & 63)] = L[(size_t)(r0 + (idx >> 6)) * DD + r0 + (idx & 63)];
        __syncthreads();

        for (int j = 0; j < NB; j++) {
            float dj = sP[j * 65 + j];
            float rs = 1.0f / sqrtf(dj);
            if (tid == 0) sLd += logf(dj);
            if (tid > j && tid < NB) sP[tid * 65 + j] *= rs;
            __syncthreads();
            int c = j + 1 + (tid & 63);
            if (c < NB) {
                float lc = sP[c * 65 + j];
                for (int r = j + 1 + (tid >> 6); r < NB; r += 4)
                    sP[r * 65 + c] -= sP[r * 65 + j] * lc;
            }
            __syncthreads();
        }
        if (tid < NB) sP[tid * 65 + tid] = sqrtf(sP[tid * 65 + tid]);
        __syncthreads();

        if (tid < NB) {
            int c = tid;
            for (int r = 0; r < NB; r++) {
                float v = (r == c) ? 1.f : 0.f;
                for (int k = c; k < r; k++) v -= sP[r * 65 + k] * sI[k * 68 + c];
                sI[r * 68 + c] = (r < c) ? 0.f : v / sP[r * 65 + r];
            }
        }
        __syncthreads();
        for (int idx = tid; idx < NB * NB; idx += 256)
            d_invDiag[((size_t)s * 4 + p) * (NB * NB) + idx] = sI[(idx >> 6) * 68 + (idx & 63)];

        const int nq = (nrows >> 6) - 1;
        for (int q = 1; q <= nq; q++) {
            const int rb = q * 64;
            float a[4][4];
#pragma unroll
            for (int r = 0; r < 4; r++)
#pragma unroll
                for (int c = 0; c < 4; c++) a[r][c] = 0.f;
#pragma unroll 4
            for (int k = 0; k < NB; k++) {
                float p0 = sP[(rb + ty * 4 + 0) * 65 + k];
                float p1 = sP[(rb + ty * 4 + 1) * 65 + k];
                float p2 = sP[(rb + ty * 4 + 2) * 65 + k];
                float p3 = sP[(rb + ty * 4 + 3) * 65 + k];
                float i0 = sI[(tx * 4 + 0) * 68 + k];
                float i1 = sI[(tx * 4 + 1) * 68 + k];
                float i2 = sI[(tx * 4 + 2) * 68 + k];
                float i3 = sI[(tx * 4 + 3) * 68 + k];
                a[0][0] += p0 * i0; a[0][1] += p0 * i1; a[0][2] += p0 * i2; a[0][3] += p0 * i3;
                a[1][0] += p1 * i0; a[1][1] += p1 * i1; a[1][2] += p1 * i2; a[1][3] += p1 * i3;
                a[2][0] += p2 * i0; a[2][1] += p2 * i1; a[2][2] += p2 * i2; a[2][3] += p2 * i3;
                a[3][0] += p3 * i0; a[3][1] += p3 * i1; a[3][2] += p3 * i2; a[3][3] += p3 * i3;
            }
            __syncthreads();
#pragma unroll
            for (int r = 0; r < 4; r++)
#pragma unroll
                for (int c = 0; c < 4; c++)
                    sP[(rb + ty * 4 + r) * 65 + tx * 4 + c] = a[r][c];
        }
        __syncthreads();

        for (int idx = tid; idx < nrows * NB; idx += 256)
            L[(size_t)(r0 + (idx >> 6)) * DD + r0 + (idx & 63)] = sP[(idx >> 6) * 65 + (idx & 63)];

        const int nt = 3 - p;
        for (int ti2 = 0; ti2 < nt; ti2++)
            for (int tj2 = 0; tj2 < nt; tj2++) {
                int lr = NB + ti2 * NB + ty * 4;
                int lc = NB + tj2 * NB + tx * 4;
                float accm[4][4];
#pragma unroll
                for (int r = 0; r < 4; r++) {
                    float4 v = *(float4*)&L[(size_t)(r0 + lr + r) * DD + r0 + lc];
                    accm[r][0] = v.x; accm[r][1] = v.y; accm[r][2] = v.z; accm[r][3] = v.w;
                }
#pragma unroll 4
                for (int k = 0; k < NB; k++) {
                    float a0 = sP[(lr + 0) * 65 + k];
                    float a1 = sP[(lr + 1) * 65 + k];
                    float a2 = sP[(lr + 2) * 65 + k];
                    float a3 = sP[(lr + 3) * 65 + k];
                    float b0 = sP[(lc + 0) * 65 + k];
                    float b1 = sP[(lc + 1) * 65 + k];
                    float b2 = sP[(lc + 2) * 65 + k];
                    float b3 = sP[(lc + 3) * 65 + k];
                    accm[0][0] -= a0 * b0; accm[0][1] -= a0 * b1; accm[0][2] -= a0 * b2; accm[0][3] -= a0 * b3;
                    accm[1][0] -= a1 * b0; accm[1][1] -= a1 * b1; accm[1][2] -= a1 * b2; accm[1][3] -= a1 * b3;
                    accm[2][0] -= a2 * b0; accm[2][1] -= a2 * b1; accm[2][2] -= a2 * b2; accm[2][3] -= a2 * b3;
                    accm[3][0] -= a3 * b0; accm[3][1] -= a3 * b1; accm[3][2] -= a3 * b2; accm[3][3] -= a3 * b3;
                }
#pragma unroll
                for (int r = 0; r < 4; r++) {
                    float4 v = make_float4(accm[r][0], accm[r][1], accm[r][2], accm[r][3]);
                    *(float4*)&L[(size_t)(r0 + lr + r) * DD + r0 + lc] = v;
                }
            }
        __syncthreads();
    }
    if (tid == 0) d_logdet[s] = sLd;
}

// ---------------------------------------------------------------------------
// Kernel 3b: explicit Linv -> bf16 hi/lo planes directly (no fp32 gmem Linv).
// Column-parallel (s, j), register double-buffer prefetch.
// dyn smem = 6 * 64*68 * 4 = 104448 B.
// ---------------------------------------------------------------------------
__global__ __launch_bounds__(256) void linv_kernel() {
    extern __shared__ float sm[];
    float* sV  = sm;                     // [3][64*68]
    float* sL2 = sm + 3 * 4352;          // [2][64*68] ping-pong
    float* sM  = sm + 5 * 4352;          // [64*68]
    const int s = blockIdx.x, j = blockIdx.y;
    const int tid = threadIdx.x, tx = tid & 15, ty = tid >> 4;
    const float* L = d_L + (size_t)s * DD * DD;
    const float* ID = d_invDiag + (size_t)s * 4 * (NB * NB);
    __nv_bfloat16* VH = d_LinvH + (size_t)s * DD * DD;
    __nv_bfloat16* VL = d_LinvL + (size_t)s * DD * DD;

    const __nv_bfloat16 z16 = __float2bfloat16(0.f);
    for (int idx = tid; idx < NB * NB; idx += 256) {
        int rr = idx >> 6, cc = idx & 63;
        float v = ID[j * NB * NB + idx];
        sV[rr * 68 + cc] = v;
        __nv_bfloat16 h = __float2bfloat16(v);
        __nv_bfloat16 l = __float2bfloat16(v - __bfloat162float(h));
        VH[(size_t)(j * 64 + rr) * DD + j * 64 + cc] = h;
        VL[(size_t)(j * 64 + rr) * DD + j * 64 + cc] = l;
        if (j == 0) { VH[(size_t)rr * DD + 64 + cc] = z16; VL[(size_t)rr * DD + 64 + cc] = z16; }
        if (j == 1) { VH[(size_t)(128 + rr) * DD + 192 + cc] = z16; VL[(size_t)(128 + rr) * DD + 192 + cc] = z16; }
        if (j == 2) {
            float v3 = ID[3 * NB * NB + idx];
            __nv_bfloat16 h3 = __float2bfloat16(v3);
            __nv_bfloat16 l3 = __float2bfloat16(v3 - __bfloat162float(h3));
            VH[(size_t)(192 + rr) * DD + 192 + cc] = h3;
            VL[(size_t)(192 + rr) * DD + 192 + cc] = l3;
        }
    }
    __syncthreads();

    const int pr = tid >> 2, pc = (tid & 3) << 4;
    float4 pf[4];
#pragma unroll
    for (int q = 0; q < 4; q++)
        pf[q] = *(const float4*)&L[(size_t)((j + 1) * 64 + pr) * DD + j * 64 + pc + q * 4];

    for (int i = j + 1; i < 4; i++) {
        float acc[4][4];
#pragma unroll
        for (int r = 0; r < 4; r++)
#pragma unroll
            for (int c = 0; c < 4; c++) acc[r][c] = 0.f;

        for (int k = j; k < i; k++) {
            float* sLb = sL2 + ((k - j) & 1) * 4352;
#pragma unroll
            for (int q = 0; q < 4; q++) *(float4*)&sLb[pr * 68 + pc + q * 4] = pf[q];
            __syncthreads();
            if (k + 1 < i) {
#pragma unroll
                for (int q = 0; q < 4; q++)
                    pf[q] = *(const float4*)&L[(size_t)(i * 64 + pr) * DD + (k + 1) * 64 + pc + q * 4];
            } else {
#pragma unroll
                for (int q = 0; q < 4; q++)
                    pf[q] = *(const float4*)&ID[(size_t)i * NB * NB + pr * 64 + pc + q * 4];
            }
            const float* Vb = sV + (k - j) * 4352;
#pragma unroll 4
            for (int kk = 0; kk < 64; kk++) {
                float a0 = sLb[(ty * 4 + 0) * 68 + kk];
                float a1 = sLb[(ty * 4 + 1) * 68 + kk];
                float a2 = sLb[(ty * 4 + 2) * 68 + kk];
                float a3 = sLb[(ty * 4 + 3) * 68 + kk];
                float4 b = *(const float4*)&Vb[kk * 68 + tx * 4];
                acc[0][0] += a0 * b.x; acc[0][1] += a0 * b.y; acc[0][2] += a0 * b.z; acc[0][3] += a0 * b.w;
                acc[1][0] += a1 * b.x; acc[1][1] += a1 * b.y; acc[1][2] += a1 * b.z; acc[1][3] += a1 * b.w;
                acc[2][0] += a2 * b.x; acc[2][1] += a2 * b.y; acc[2][2] += a2 * b.z; acc[2][3] += a2 * b.w;
                acc[3][0] += a3 * b.x; acc[3][1] += a3 * b.y; acc[3][2] += a3 * b.z; acc[3][3] += a3 * b.w;
            }
        }

        const int b2 = (i - j) & 1;
        float* sLb2 = sL2 + b2 * 4352;
#pragma unroll
        for (int q = 0; q < 4; q++) *(float4*)&sLb2[pr * 68 + pc + q * 4] = pf[q];
#pragma unroll
        for (int r = 0; r < 4; r++)
#pragma unroll
            for (int c = 0; c < 4; c++) sM[(ty * 4 + r) * 68 + tx * 4 + c] = acc[r][c];
        __syncthreads();
        if (i < 3) {
#pragma unroll
            for (int q = 0; q < 4; q++)
                pf[q] = *(const float4*)&L[(size_t)((i + 1) * 64 + pr) * DD + j * 64 + pc + q * 4];
        }
        float o[4][4];
#pragma unroll
        for (int r = 0; r < 4; r++)
#pragma unroll
            for (int c = 0; c < 4; c++) o[r][c] = 0.f;
#pragma unroll 4
        for (int kk = 0; kk < 64; kk++) {
            float a0 = sLb2[(ty * 4 + 0) * 68 + kk];
            float a1 = sLb2[(ty * 4 + 1) * 68 + kk];
            float a2 = sLb2[(ty * 4 + 2) * 68 + kk];
            float a3 = sLb2[(ty * 4 + 3) * 68 + kk];
            float4 b = *(const float4*)&sM[kk * 68 + tx * 4];
            o[0][0] -= a0 * b.x; o[0][1] -= a0 * b.y; o[0][2] -= a0 * b.z; o[0][3] -= a0 * b.w;
            o[1][0] -= a1 * b.x; o[1][1] -= a1 * b.y; o[1][2] -= a1 * b.z; o[1][3] -= a1 * b.w;
            o[2][0] -= a2 * b.x; o[2][1] -= a2 * b.y; o[2][2] -= a2 * b.z; o[2][3] -= a2 * b.w;
            o[3][0] -= a3 * b.x; o[3][1] -= a3 * b.y; o[3][2] -= a3 * b.z; o[3][3] -= a3 * b.w;
        }
        __syncthreads();
#pragma unroll
        for (int r = 0; r < 4; r++) {
            uint2 hi, lo;
            cvt_split(make_float4(o[r][0], o[r][1], o[r][2], o[r][3]), hi, lo);
            size_t goff = (size_t)(i * 64 + ty * 4 + r) * DD + j * 64 + tx * 4;
            *(uint2*)&VH[goff] = hi;
            *(uint2*)&VL[goff] = lo;
            if (i < 3) *(float4*)&sV[(i - j) * 4352 + (ty * 4 + r) * 68 + tx * 4] =
                make_float4(o[r][0], o[r][1], o[r][2], o[r][3]);
        }
        __syncthreads();
    }
}

// ---------------------------------------------------------------------------
// Kernel 3c: w[s][d] = sum_k Linv[s][d][k] * mu[s][k]  (from bf16 planes)
// ---------------------------------------------------------------------------
__global__ __launch_bounds__(256) void wvec_kernel(const float* __restrict__ mu) {
    __shared__ float smu[DD];
    const int s = blockIdx.x, tid = threadIdx.x, wid = tid >> 5, lane = tid & 31;
    smu[tid] = mu[(size_t)s * DD + tid];
    __syncthreads();
    const __nv_bfloat162* H = (const __nv_bfloat162*)(d_LinvH + (size_t)s * DD * DD);
    const __nv_bfloat162* Lp = (const __nv_bfloat162*)(d_LinvL + (size_t)s * DD * DD);
    for (int row = wid * 32; row < (wid + 1) * 32; row++) {
        float acc = 0.f;
#pragma unroll
        for (int q = 0; q < 4; q++) {
            int k2 = lane + 32 * q;
            __nv_bfloat162 hv = H[(size_t)row * 128 + k2];
            __nv_bfloat162 lv = Lp[(size_t)row * 128 + k2];
            acc += (__bfloat162float(hv.x) + __bfloat162float(lv.x)) * smu[2 * k2]
                 + (__bfloat162float(hv.y) + __bfloat162float(lv.y)) * smu[2 * k2 + 1];
        }
#pragma unroll
        for (int o = 16; o > 0; o >>= 1) acc += __shfl_xor_sync(0xFFFFFFFF, acc, o);
        if (lane == 0) d_w[(size_t)s * DD + row] = acc;
    }
}

// ---------------------------------------------------------------------------
// Kernel 4a: out[b][s] = -0.5*(D*log2pi + logdet[s])
// ---------------------------------------------------------------------------
__global__ __launch_bounds__(256) void init_out_kernel(float* __restrict__ out) {
    const float log2pi = 1.8378770664093453f;
    int b = blockIdx.x, s = threadIdx.x;
    out[(size_t)b * SS + s] = -0.5f * ((float)DD * log2pi + d_logdet[s]);
}

// ---------------------------------------------------------------------------
// Kernel 4b: Z = Linv_half * x^T via cp.async double-buffered bf16-split MMA;
// maha += colsum((Z - w)^2). All operands pre-split bf16 (pure-copy staging).
// smem: 2 bufs x 4 planes x [128][72] bf16 = 147456 B, + w[128] + red[512] fl.
// ---------------------------------------------------------------------------
#define LDA 72
#define PLANE (128 * LDA)
#define BUFE (4 * PLANE)
__global__ __launch_bounds__(256) void mahaZ_kernel(float* __restrict__ out) {
    extern __shared__ __nv_bfloat16 smh[];
    const uint32_t sbase = smem_u32(smh);
    float* sW = (float*)(smh + 2 * BUFE);       // 128 floats
    float* sRed = sW + 128;                      // 512 floats
    const int tid = threadIdx.x, wid = tid >> 5, lane = tid & 31;
    const int wm = wid & 3, wn = wid >> 2;
    const int b0 = blockIdx.x * 128, h = blockIdx.y, s = blockIdx.z;
    const int nchunks = 2 * (h + 1);

    const __nv_bfloat16* AH = d_LinvH + ((size_t)s * DD + h * 128) * DD;
    const __nv_bfloat16* AL = d_LinvL + ((size_t)s * DD + h * 128) * DD;
    const __nv_bfloat16* BH = d_xH + (size_t)b0 * DD;
    const __nv_bfloat16* BL = d_xL + (size_t)b0 * DD;

    if (tid < 128) sW[tid] = d_w[(size_t)s * DD + h * 128 + tid];

    float acc[2][8][4];
#pragma unroll
    for (int i = 0; i < 2; i++)
#pragma unroll
        for (int j = 0; j < 8; j++)
#pragma unroll
            for (int r = 0; r < 4; r++) acc[i][j][r] = 0.f;

    const uint32_t aRow = wm * 32 + (lane & 15);
    const uint32_t aColOff = ((lane >> 4) << 3);
    const uint32_t bRow = wn * 64 + (lane & 7) + ((lane >> 4) << 3);
    const uint32_t bColOff = (((lane >> 3) & 1) << 3);

    // staging: 16 cp.async of 16B per thread per chunk (4 planes x 4 steps)
#define ISSUE_CHUNK(c, buf) do {                                              \
    const int _k0 = (c) * 64;                                                 \
    const uint32_t _bb = sbase + (uint32_t)(buf) * (BUFE * 2);                \
    _Pragma("unroll")                                                         \
    for (int st = 0; st < 4; st++) {                                          \
        int rem = tid + 256 * st;                                             \
        int row = rem >> 3, q8 = (rem & 7) << 3;                              \
        uint32_t doff = (uint32_t)(row * LDA + q8) * 2;                       \
        size_t goff = (size_t)row * DD + _k0 + q8;                            \
        CP_ASYNC16(_bb + 0 * (PLANE * 2) + doff, AH + goff);                  \
        CP_ASYNC16(_bb + 1 * (PLANE * 2) + doff, AL + goff);                  \
        CP_ASYNC16(_bb + 2 * (PLANE * 2) + doff, BH + goff);                  \
        CP_ASYNC16(_bb + 3 * (PLANE * 2) + doff, BL + goff);                  \
    }                                                                         \
    asm volatile("cp.async.commit_group;");                                   \
} while (0)

    ISSUE_CHUNK(0, 0);
    for (int c = 0; c < nchunks; c++) {
        if (c + 1 < nchunks) {
            ISSUE_CHUNK(c + 1, (c + 1) & 1);
            asm volatile("cp.async.wait_group 1;");
        } else {
            asm volatile("cp.async.wait_group 0;");
        }
        __syncthreads();
        const uint32_t AHIb = sbase + (uint32_t)(c & 1) * (BUFE * 2);
        const uint32_t ALOb = AHIb + PLANE * 2;
        const uint32_t BHIb = AHIb + 2 * (PLANE * 2);
        const uint32_t BLOb = AHIb + 3 * (PLANE * 2);
#pragma unroll
        for (int ks = 0; ks < 4; ks++) {
            const uint32_t kc = ks * 16;
            uint32_t ahi[2][4], alo[2][4];
#pragma unroll
            for (int i = 0; i < 2; i++) {
                uint32_t ra = ((aRow + i * 16) * LDA + kc + aColOff) * 2;
                ldsm_x4(ahi[i][0], ahi[i][1], ahi[i][2], ahi[i][3], AHIb + ra);
                ldsm_x4(alo[i][0], alo[i][1], alo[i][2], alo[i][3], ALOb + ra);
            }
#pragma unroll
            for (int p = 0; p < 4; p++) {
                uint32_t bhi[4], blo[4];
                uint32_t rb = ((bRow + p * 16) * LDA + kc + bColOff) * 2;
                ldsm_x4(bhi[0], bhi[1], bhi[2], bhi[3], BHIb + rb);
                ldsm_x4(blo[0], blo[1], blo[2], blo[3], BLOb + rb);
#pragma unroll
                for (int i = 0; i < 2; i++) {
                    mma_bf16(acc[i][2 * p + 0], ahi[i], bhi[0], bhi[1]);
                    mma_bf16(acc[i][2 * p + 1], ahi[i], bhi[2], bhi[3]);
                    mma_bf16(acc[i][2 * p + 0], ahi[i], blo[0], blo[1]);
                    mma_bf16(acc[i][2 * p + 1], ahi[i], blo[2], blo[3]);
                    mma_bf16(acc[i][2 * p + 0], alo[i], bhi[0], bhi[1]);
                    mma_bf16(acc[i][2 * p + 1], alo[i], bhi[2], bhi[3]);
                }
            }
        }
        __syncthreads();
    }

    // epilogue: y = Z - w(row); column sums of y^2
    const int crow = lane >> 2;
    float wv[2][2];
#pragma unroll
    for (int i = 0; i < 2; i++) {
        wv[i][0] = sW[wm * 32 + i * 16 + crow];
        wv[i][1] = sW[wm * 32 + i * 16 + crow + 8];
    }
    float cs0[8], cs1[8];
#pragma unroll
    for (int j = 0; j < 8; j++) {
        float s0 = 0.f, s1 = 0.f;
#pragma unroll
        for (int i = 0; i < 2; i++) {
            float y0 = acc[i][j][0] - wv[i][0];
            float y1 = acc[i][j][1] - wv[i][0];
            float y2 = acc[i][j][2] - wv[i][1];
            float y3 = acc[i][j][3] - wv[i][1];
            s0 += y0 * y0 + y2 * y2;
            s1 += y1 * y1 + y3 * y3;
        }
#pragma unroll
        for (int o = 4; o <= 16; o <<= 1) {
            s0 += __shfl_xor_sync(0xFFFFFFFF, s0, o);
            s1 += __shfl_xor_sync(0xFFFFFFFF, s1, o);
        }
        cs0[j] = s0; cs1[j] = s1;
    }
    if (lane < 4) {
#pragma unroll
        for (int j = 0; j < 8; j++) {
            sRed[wid * 64 + j * 8 + 2 * lane + 0] = cs0[j];
            sRed[wid * 64 + j * 8 + 2 * lane + 1] = cs1[j];
        }
    }
    __syncthreads();
    if (tid < 128) {
        int nn = tid & 63, g = (tid >> 6) * 4;
        float m = sRed[(g + 0) * 64 + nn] + sRed[(g + 1) * 64 + nn]
                + sRed[(g + 2) * 64 + nn] + sRed[(g + 3) * 64 + nn];
        atomicAdd(&out[(size_t)(b0 + tid) * SS + s], -0.5f * m);
    }
}

// ---------------------------------------------------------------------------
extern "C" void kernel_launch(void* const* d_in, const int* in_sizes, int n_in,
                              void* d_out, int out_size) {
    const float* x  = (const float*)d_in[0];   // (1024, 256)
    const float* mu = (const float*)d_in[1];   // (256, 1, 256)
    const float* sg = (const float*)d_in[2];   // (256, 1, 256, 256)
    float* out = (float*)d_out;                // (1024, 256)

    cudaFuncSetAttribute(syrk_kernel,  cudaFuncAttributeMaxDynamicSharedMemorySize, 67584);
    cudaFuncSetAttribute(chol_kernel,  cudaFuncAttributeMaxDynamicSharedMemorySize, 83968);
    cudaFuncSetAttribute(linv_kernel,  cudaFuncAttributeMaxDynamicSharedMemorySize, 104448);
    cudaFuncSetAttribute(mahaZ_kernel, cudaFuncAttributeMaxDynamicSharedMemorySize, 150016);

    ridge_kernel<<<SS, 256>>>(sg);
    xcvt_kernel<<<256, 256>>>(x);
    syrk_kernel<<<dim3(3, SS), 256, 67584>>>(sg);
    chol_kernel<<<SS, 256, 83968>>>();
    linv_kernel<<<dim3(SS, 3), 256, 104448>>>();
    wvec_kernel<<<SS, 256>>>(mu);
    init_out_kernel<<<1024, 256>>>(out);
    mahaZ_kernel<<<dim3(8, 2, SS), 256, 150016>>>(out);
}

// round 17
// speedup vs baseline: 1.1433x; 1.1433x over previous
#include <cuda_runtime.h>
#include <cuda_bf16.h>
#include <math.h>
#include <stdint.h>

#define DD 256
#define SS 256
#define NB 64

// Scratch (device globals; no allocation allowed)
__device__ float d_L[(size_t)SS * DD * DD];                 // 64 MB: Sigma -> L (lower valid)
__device__ float d_invDiag[(size_t)SS * 4 * NB * NB];       // inv of diag 64x64 blocks
__device__ __nv_bfloat16 d_LinvH[(size_t)SS * DD * DD];     // 32 MB: hi plane of L^-1
__device__ __nv_bfloat16 d_LinvL[(size_t)SS * DD * DD];     // 32 MB: lo plane of L^-1
__device__ __nv_bfloat16 d_xH[(size_t)1024 * DD];           // x hi plane
__device__ __nv_bfloat16 d_xL[(size_t)1024 * DD];           // x lo plane
__device__ float d_w[(size_t)SS * DD];                      // w = Linv * mu
__device__ float d_ridge[SS];
__device__ float d_logdet[SS];

// ======================= PTX helpers (sm_80-level only) =======================
__device__ __forceinline__ uint32_t smem_u32(const void* p) {
    uint32_t a;
    asm("{ .reg .u64 t; cvta.to.shared.u64 t, %1; cvt.u32.u64 %0, t; }" : "=r"(a) : "l"(p));
    return a;
}
__device__ __forceinline__ void ldsm_x4(uint32_t& r0, uint32_t& r1, uint32_t& r2, uint32_t& r3,
                                        uint32_t addr) {
    asm volatile("ldmatrix.sync.aligned.m8n8.x4.shared.b16 {%0,%1,%2,%3}, [%4];"
                 : "=r"(r0), "=r"(r1), "=r"(r2), "=r"(r3) : "r"(addr));
}
__device__ __forceinline__ void ldsm_x4t(uint32_t& r0, uint32_t& r1, uint32_t& r2, uint32_t& r3,
                                         uint32_t addr) {
    asm volatile("ldmatrix.sync.aligned.m8n8.x4.trans.shared.b16 {%0,%1,%2,%3}, [%4];"
                 : "=r"(r0), "=r"(r1), "=r"(r2), "=r"(r3) : "r"(addr));
}
__device__ __forceinline__ void mma_bf16(float* d, const uint32_t* a, uint32_t b0, uint32_t b1) {
    asm volatile("mma.sync.aligned.m16n8k16.row.col.f32.bf16.bf16.f32 "
                 "{%0,%1,%2,%3}, {%4,%5,%6,%7}, {%8,%9}, {%0,%1,%2,%3};"
                 : "+f"(d[0]), "+f"(d[1]), "+f"(d[2]), "+f"(d[3])
                 : "r"(a[0]), "r"(a[1]), "r"(a[2]), "r"(a[3]), "r"(b0), "r"(b1));
}
__device__ __forceinline__ void cvt_split(float4 v, uint2& hi, uint2& lo) {
    __nv_bfloat16 h0 = __float2bfloat16(v.x), h1 = __float2bfloat16(v.y),
                  h2 = __float2bfloat16(v.z), h3 = __float2bfloat16(v.w);
    __nv_bfloat16 l0 = __float2bfloat16(v.x - __bfloat162float(h0));
    __nv_bfloat16 l1 = __float2bfloat16(v.y - __bfloat162float(h1));
    __nv_bfloat16 l2 = __float2bfloat16(v.z - __bfloat162float(h2));
    __nv_bfloat16 l3 = __float2bfloat16(v.w - __bfloat162float(h3));
    __nv_bfloat162 ph0 = __halves2bfloat162(h0, h1), ph1 = __halves2bfloat162(h2, h3);
    __nv_bfloat162 pl0 = __halves2bfloat162(l0, l1), pl1 = __halves2bfloat162(l2, l3);
    hi.x = *(uint32_t*)&ph0; hi.y = *(uint32_t*)&ph1;
    lo.x = *(uint32_t*)&pl0; lo.y = *(uint32_t*)&pl1;
}
#define CP_ASYNC16(dst, src) \
    asm volatile("cp.async.cg.shared.global [%0], [%1], 16;" :: "r"(dst), "l"(src))

// ---------------------------------------------------------------------------
// Kernel 1: ridge[s] = 0.01 * ||sp_s||_F^2 / D
// ---------------------------------------------------------------------------
__global__ __launch_bounds__(256) void ridge_kernel(const float* __restrict__ sp) {
    const int s = blockIdx.x;
    const float* A = sp + (size_t)s * DD * DD;
    float acc = 0.f;
    for (int i = threadIdx.x; i < DD * DD; i += 256) { float v = A[i]; acc += v * v; }
    __shared__ float red[256];
    red[threadIdx.x] = acc; __syncthreads();
    for (int o = 128; o > 0; o >>= 1) {
        if (threadIdx.x < o) red[threadIdx.x] += red[threadIdx.x + o];
        __syncthreads();
    }
    if (threadIdx.x == 0) d_ridge[s] = 0.01f * red[0] / (float)DD;
}

// ---------------------------------------------------------------------------
// Kernel 1b: x -> bf16 hi/lo planes
// ---------------------------------------------------------------------------
__global__ __launch_bounds__(256) void xcvt_kernel(const float* __restrict__ x) {
    int idx = blockIdx.x * 256 + threadIdx.x;        // 65536 float4s
    float4 v = ((const float4*)x)[idx];
    uint2 hi, lo; cvt_split(v, hi, lo);
    ((uint2*)d_xH)[idx] = hi;
    ((uint2*)d_xL)[idx] = lo;
}

// ---------------------------------------------------------------------------
// Kernel 2: Sigma_s = sp^T sp + ridge*I via mma.sync bf16-split.
// ---------------------------------------------------------------------------
#define SLDK 264
__global__ __launch_bounds__(256) void syrk_kernel(const float* __restrict__ sp) {
    extern __shared__ __nv_bfloat16 smh[];
    const uint32_t sbase = smem_u32(smh);
    const uint32_t LO = 64 * SLDK;
    const int t = blockIdx.x;
    const int ti = (t + 1) >> 1, tj = t >> 1;   // (0,0),(1,0),(1,1)
    const int s = blockIdx.y;
    const float* A = sp + (size_t)s * DD * DD;
    float* C = d_L + (size_t)s * DD * DD;

    const int tid = threadIdx.x, wid = tid >> 5, lane = tid & 31;
    const int wm = wid & 3, wn = wid >> 2;
    const int dlo = (ti == tj) ? ti * 128 : 0;
    const int dw  = (ti == tj) ? 128 : 256;
    const int gm0 = ti * 128 + wm * 32, gn0 = tj * 128 + wn * 64;
    const int lm0 = gm0 - dlo, ln0 = gn0 - dlo;

    const int lt = lane >> 3, lr = lane & 7;
    const uint32_t aK = lr + 8 * (lt >> 1), aM = 8 * (lt & 1);
    const uint32_t bK = lr + 8 * (lt & 1),  bN = 8 * (lt >> 1);

    float acc[2][8][4];
#pragma unroll
    for (int i = 0; i < 2; i++)
#pragma unroll
        for (int j = 0; j < 8; j++)
#pragma unroll
            for (int r = 0; r < 4; r++) acc[i][j][r] = 0.f;

    for (int k0 = 0; k0 < DD; k0 += 64) {
        for (int idx = tid; idx < 16 * dw; idx += 256) {
            int k = idx / (dw >> 2), dq = (idx % (dw >> 2)) << 2;
            float4 v = *(const float4*)(A + (size_t)(k0 + k) * DD + dlo + dq);
            uint2 hi, lo; cvt_split(v, hi, lo);
            *(uint2*)(smh + k * SLDK + dq) = hi;
            *(uint2*)(smh + LO + k * SLDK + dq) = lo;
        }
        __syncthreads();
#pragma unroll
        for (int ks = 0; ks < 4; ks++) {
            const uint32_t kc = ks * 16;
            uint32_t ahi[2][4], alo[2][4];
#pragma unroll
            for (int i = 0; i < 2; i++) {
                uint32_t ra = (kc + aK) * SLDK + lm0 + i * 16 + aM;
                ldsm_x4t(ahi[i][0], ahi[i][1], ahi[i][2], ahi[i][3], sbase + ra * 2);
                ldsm_x4t(alo[i][0], alo[i][1], alo[i][2], alo[i][3], sbase + (LO + ra) * 2);
            }
#pragma unroll
            for (int p = 0; p < 4; p++) {
                uint32_t bhi[4], blo[4];
                uint32_t rb = (kc + bK) * SLDK + ln0 + p * 16 + bN;
                ldsm_x4t(bhi[0], bhi[1], bhi[2], bhi[3], sbase + rb * 2);
                ldsm_x4t(blo[0], blo[1], blo[2], blo[3], sbase + (LO + rb) * 2);
#pragma unroll
                for (int i = 0; i < 2; i++) {
                    mma_bf16(acc[i][2 * p + 0], ahi[i], bhi[0], bhi[1]);
                    mma_bf16(acc[i][2 * p + 1], ahi[i], bhi[2], bhi[3]);
                    mma_bf16(acc[i][2 * p + 0], ahi[i], blo[0], blo[1]);
                    mma_bf16(acc[i][2 * p + 1], ahi[i], blo[2], blo[3]);
                    mma_bf16(acc[i][2 * p + 0], alo[i], bhi[0], bhi[1]);
                    mma_bf16(acc[i][2 * p + 1], alo[i], bhi[2], bhi[3]);
                }
            }
        }
        __syncthreads();
    }

    const float ridge = d_ridge[s];
    const int crow = lane >> 2, ccol = 2 * (lane & 3);
#pragma unroll
    for (int i = 0; i < 2; i++)
#pragma unroll
        for (int j = 0; j < 8; j++) {
            int row = gm0 + i * 16 + crow;
            int col = gn0 + j * 8 + ccol;
            float c0 = acc[i][j][0], c1 = acc[i][j][1], c2 = acc[i][j][2], c3 = acc[i][j][3];
            if (row == col) c0 += ridge;
            if (row == col + 1) c1 += ridge;
            if (row + 8 == col) c2 += ridge;
            if (row + 8 == col + 1) c3 += ridge;
            *(float2*)&C[(size_t)row * DD + col] = make_float2(c0, c1);
            *(float2*)&C[(size_t)(row + 8) * DD + col] = make_float2(c2, c3);
        }
}

// ---------------------------------------------------------------------------
// Kernel 3: per-s blocked Cholesky, v3.
//  - diag factor: Gaussian elimination, ONE sync per column, scale at end
//  - invD: blocked 16x16 parallel triangular inversion (4 diag solves + 3
//    GEMM levels), all 256 threads busy
//  - L21 via GEMM with invD^T; trailing update as before
// smem = (256*65 + 64*68 + 64 + 3*16*17)*4 = 87488 B.
// ---------------------------------------------------------------------------
__global__ __launch_bounds__(256) void chol_kernel() {
    extern __shared__ float sm[];
    float* sP  = sm;                       // 256*65 panel
    float* sI  = sm + 256 * 65;            // 64*68 invD
    float* sRS = sI + 64 * 68;             // 64 rsqrt of diag
    float* sMM = sRS + 64;                 // 3*16*17 level scratch
    __shared__ float sLd;
    const int s = blockIdx.x;
    const int tid = threadIdx.x;
    const int tx = tid & 15, ty = tid >> 4;
    float* L = d_L + (size_t)s * DD * DD;
    if (tid == 0) sLd = 0.f;

    for (int p = 0; p < 4; p++) {
        const int r0 = p * NB;
        const int nrows = DD - r0;
        for (int idx = tid; idx < nrows * NB; idx += 256)
            sP[(idx >> 6) * 65 + (idx & 63)] = L[(size_t)(r0 + (idx >> 6)) * DD + r0 + (idx & 63)];
        __syncthreads();

        // --- diag block factor: unnormalized Gaussian elimination, 1 sync/col ---
        const int fc = tid & 63;
        const int fr0 = tid >> 6;           // 0..3
        for (int j = 0; j < NB; j++) {
            float dj = sP[j * 65 + j];
            if (tid == 0) sLd += logf(dj);
            if (fc > j) {
                float mult = sP[fc * 65 + j] * __fdividef(1.0f, dj);
                for (int r = j + 1 + fr0; r < NB; r += 4)
                    sP[r * 65 + fc] -= sP[r * 65 + j] * mult;
            }
            __syncthreads();
        }
        // scale to true Cholesky: L[r][c] = A[r][c] * rsqrt(d_c)
        if (tid < NB) sRS[tid] = rsqrtf(sP[tid * 65 + tid]);
        __syncthreads();
        for (int idx = tid; idx < NB * NB; idx += 256) {
            int r = idx >> 6, c = idx & 63;
            if (r >= c) sP[r * 65 + c] *= sRS[c];
        }
        __syncthreads();

        // --- blocked invD: zero, 4x 16-col solves, 3 GEMM levels ---
        for (int idx = tid; idx < 64 * 68; idx += 256) sI[idx] = 0.f;
        __syncthreads();
        if (tid < NB) {
            int b = tid >> 4, c = tid & 15, o = b * 16;
            for (int r = c; r < 16; r++) {
                float v = (r == c) ? 1.f : 0.f;
                for (int k = c; k < r; k++)
                    v -= sP[(o + r) * 65 + o + k] * sI[(o + k) * 68 + o + c];
                sI[(o + r) * 68 + o + c] = v / sP[(o + r) * 65 + o + r];
            }
        }
        __syncthreads();
        for (int lev = 1; lev <= 3; lev++) {
            int nb = 4 - lev;
            for (int e = tid; e < nb * 256; e += 256) {
                int blk = e >> 8, r = (e >> 4) & 15, c = e & 15;
                int j = blk, i = blk + lev;
                float m = 0.f;
                for (int kk = j * 16; kk < i * 16; kk++)
                    m += sP[(i * 16 + r) * 65 + kk] * sI[kk * 68 + j * 16 + c];
                sMM[blk * 272 + r * 17 + c] = m;
            }
            __syncthreads();
            for (int e = tid; e < nb * 256; e += 256) {
                int blk = e >> 8, r = (e >> 4) & 15, c = e & 15;
                int j = blk, i = blk + lev;
                float v = 0.f;
                for (int t = 0; t <= r; t++)
                    v -= sI[(i * 16 + r) * 68 + i * 16 + t] * sMM[blk * 272 + t * 17 + c];
                sI[(i * 16 + r) * 68 + j * 16 + c] = v;
            }
            __syncthreads();
        }
        for (int idx = tid; idx < NB * NB; idx += 256)
            d_invDiag[((size_t)s * 4 + p) * (NB * NB) + idx] = sI[(idx >> 6) * 68 + (idx & 63)];

        // --- L21 = A21 * invD^T (in-place in sP) ---
        const int nq = (nrows >> 6) - 1;
        for (int q = 1; q <= nq; q++) {
            const int rb = q * 64;
            float a[4][4];
#pragma unroll
            for (int r = 0; r < 4; r++)
#pragma unroll
                for (int c = 0; c < 4; c++) a[r][c] = 0.f;
#pragma unroll 4
            for (int k = 0; k < NB; k++) {
                float p0 = sP[(rb + ty * 4 + 0) * 65 + k];
                float p1 = sP[(rb + ty * 4 + 1) * 65 + k];
                float p2 = sP[(rb + ty * 4 + 2) * 65 + k];
                float p3 = sP[(rb + ty * 4 + 3) * 65 + k];
                float i0 = sI[(tx * 4 + 0) * 68 + k];
                float i1 = sI[(tx * 4 + 1) * 68 + k];
                float i2 = sI[(tx * 4 + 2) * 68 + k];
                float i3 = sI[(tx * 4 + 3) * 68 + k];
                a[0][0] += p0 * i0; a[0][1] += p0 * i1; a[0][2] += p0 * i2; a[0][3] += p0 * i3;
                a[1][0] += p1 * i0; a[1][1] += p1 * i1; a[1][2] += p1 * i2; a[1][3] += p1 * i3;
                a[2][0] += p2 * i0; a[2][1] += p2 * i1; a[2][2] += p2 * i2; a[2][3] += p2 * i3;
                a[3][0] += p3 * i0; a[3][1] += p3 * i1; a[3][2] += p3 * i2; a[3][3] += p3 * i3;
            }
            __syncthreads();
#pragma unroll
            for (int r = 0; r < 4; r++)
#pragma unroll
                for (int c = 0; c < 4; c++)
                    sP[(rb + ty * 4 + r) * 65 + tx * 4 + c] = a[r][c];
        }
        __syncthreads();

        for (int idx = tid; idx < nrows * NB; idx += 256)
            L[(size_t)(r0 + (idx >> 6)) * DD + r0 + (idx & 63)] = sP[(idx >> 6) * 65 + (idx & 63)];

        const int nt = 3 - p;
        for (int ti2 = 0; ti2 < nt; ti2++)
            for (int tj2 = 0; tj2 < nt; tj2++) {
                int lr = NB + ti2 * NB + ty * 4;
                int lc = NB + tj2 * NB + tx * 4;
                float accm[4][4];
#pragma unroll
                for (int r = 0; r < 4; r++) {
                    float4 v = *(float4*)&L[(size_t)(r0 + lr + r) * DD + r0 + lc];
                    accm[r][0] = v.x; accm[r][1] = v.y; accm[r][2] = v.z; accm[r][3] = v.w;
                }
#pragma unroll 4
                for (int k = 0; k < NB; k++) {
                    float a0 = sP[(lr + 0) * 65 + k];
                    float a1 = sP[(lr + 1) * 65 + k];
                    float a2 = sP[(lr + 2) * 65 + k];
                    float a3 = sP[(lr + 3) * 65 + k];
                    float b0 = sP[(lc + 0) * 65 + k];
                    float b1 = sP[(lc + 1) * 65 + k];
                    float b2 = sP[(lc + 2) * 65 + k];
                    float b3 = sP[(lc + 3) * 65 + k];
                    accm[0][0] -= a0 * b0; accm[0][1] -= a0 * b1; accm[0][2] -= a0 * b2; accm[0][3] -= a0 * b3;
                    accm[1][0] -= a1 * b0; accm[1][1] -= a1 * b1; accm[1][2] -= a1 * b2; accm[1][3] -= a1 * b3;
                    accm[2][0] -= a2 * b0; accm[2][1] -= a2 * b1; accm[2][2] -= a2 * b2; accm[2][3] -= a2 * b3;
                    accm[3][0] -= a3 * b0; accm[3][1] -= a3 * b1; accm[3][2] -= a3 * b2; accm[3][3] -= a3 * b3;
                }
#pragma unroll
                for (int r = 0; r < 4; r++) {
                    float4 v = make_float4(accm[r][0], accm[r][1], accm[r][2], accm[r][3]);
                    *(float4*)&L[(size_t)(r0 + lr + r) * DD + r0 + lc] = v;
                }
            }
        __syncthreads();
    }
    if (tid == 0) d_logdet[s] = sLd;
}

// ---------------------------------------------------------------------------
// Kernel 3b: explicit Linv -> bf16 hi/lo planes directly (no fp32 gmem Linv).
// Column-parallel (s, j), register double-buffer prefetch.
// dyn smem = 6 * 64*68 * 4 = 104448 B.
// ---------------------------------------------------------------------------
__global__ __launch_bounds__(256) void linv_kernel() {
    extern __shared__ float sm[];
    float* sV  = sm;                     // [3][64*68]
    float* sL2 = sm + 3 * 4352;          // [2][64*68] ping-pong
    float* sM  = sm + 5 * 4352;          // [64*68]
    const int s = blockIdx.x, j = blockIdx.y;
    const int tid = threadIdx.x, tx = tid & 15, ty = tid >> 4;
    const float* L = d_L + (size_t)s * DD * DD;
    const float* ID = d_invDiag + (size_t)s * 4 * (NB * NB);
    __nv_bfloat16* VH = d_LinvH + (size_t)s * DD * DD;
    __nv_bfloat16* VL = d_LinvL + (size_t)s * DD * DD;

    const __nv_bfloat16 z16 = __float2bfloat16(0.f);
    for (int idx = tid; idx < NB * NB; idx += 256) {
        int rr = idx >> 6, cc = idx & 63;
        float v = ID[j * NB * NB + idx];
        sV[rr * 68 + cc] = v;
        __nv_bfloat16 h = __float2bfloat16(v);
        __nv_bfloat16 l = __float2bfloat16(v - __bfloat162float(h));
        VH[(size_t)(j * 64 + rr) * DD + j * 64 + cc] = h;
        VL[(size_t)(j * 64 + rr) * DD + j * 64 + cc] = l;
        if (j == 0) { VH[(size_t)rr * DD + 64 + cc] = z16; VL[(size_t)rr * DD + 64 + cc] = z16; }
        if (j == 1) { VH[(size_t)(128 + rr) * DD + 192 + cc] = z16; VL[(size_t)(128 + rr) * DD + 192 + cc] = z16; }
        if (j == 2) {
            float v3 = ID[3 * NB * NB + idx];
            __nv_bfloat16 h3 = __float2bfloat16(v3);
            __nv_bfloat16 l3 = __float2bfloat16(v3 - __bfloat162float(h3));
            VH[(size_t)(192 + rr) * DD + 192 + cc] = h3;
            VL[(size_t)(192 + rr) * DD + 192 + cc] = l3;
        }
    }
    __syncthreads();

    const int pr = tid >> 2, pc = (tid & 3) << 4;
    float4 pf[4];
#pragma unroll
    for (int q = 0; q < 4; q++)
        pf[q] = *(const float4*)&L[(size_t)((j + 1) * 64 + pr) * DD + j * 64 + pc + q * 4];

    for (int i = j + 1; i < 4; i++) {
        float acc[4][4];
#pragma unroll
        for (int r = 0; r < 4; r++)
#pragma unroll
            for (int c = 0; c < 4; c++) acc[r][c] = 0.f;

        for (int k = j; k < i; k++) {
            float* sLb = sL2 + ((k - j) & 1) * 4352;
#pragma unroll
            for (int q = 0; q < 4; q++) *(float4*)&sLb[pr * 68 + pc + q * 4] = pf[q];
            __syncthreads();
            if (k + 1 < i) {
#pragma unroll
                for (int q = 0; q < 4; q++)
                    pf[q] = *(const float4*)&L[(size_t)(i * 64 + pr) * DD + (k + 1) * 64 + pc + q * 4];
            } else {
#pragma unroll
                for (int q = 0; q < 4; q++)
                    pf[q] = *(const float4*)&ID[(size_t)i * NB * NB + pr * 64 + pc + q * 4];
            }
            const float* Vb = sV + (k - j) * 4352;
#pragma unroll 4
            for (int kk = 0; kk < 64; kk++) {
                float a0 = sLb[(ty * 4 + 0) * 68 + kk];
                float a1 = sLb[(ty * 4 + 1) * 68 + kk];
                float a2 = sLb[(ty * 4 + 2) * 68 + kk];
                float a3 = sLb[(ty * 4 + 3) * 68 + kk];
                float4 b = *(const float4*)&Vb[kk * 68 + tx * 4];
                acc[0][0] += a0 * b.x; acc[0][1] += a0 * b.y; acc[0][2] += a0 * b.z; acc[0][3] += a0 * b.w;
                acc[1][0] += a1 * b.x; acc[1][1] += a1 * b.y; acc[1][2] += a1 * b.z; acc[1][3] += a1 * b.w;
                acc[2][0] += a2 * b.x; acc[2][1] += a2 * b.y; acc[2][2] += a2 * b.z; acc[2][3] += a2 * b.w;
                acc[3][0] += a3 * b.x; acc[3][1] += a3 * b.y; acc[3][2] += a3 * b.z; acc[3][3] += a3 * b.w;
            }
        }

        const int b2 = (i - j) & 1;
        float* sLb2 = sL2 + b2 * 4352;
#pragma unroll
        for (int q = 0; q < 4; q++) *(float4*)&sLb2[pr * 68 + pc + q * 4] = pf[q];
#pragma unroll
        for (int r = 0; r < 4; r++)
#pragma unroll
            for (int c = 0; c < 4; c++) sM[(ty * 4 + r) * 68 + tx * 4 + c] = acc[r][c];
        __syncthreads();
        if (i < 3) {
#pragma unroll
            for (int q = 0; q < 4; q++)
                pf[q] = *(const float4*)&L[(size_t)((i + 1) * 64 + pr) * DD + j * 64 + pc + q * 4];
        }
        float o[4][4];
#pragma unroll
        for (int r = 0; r < 4; r++)
#pragma unroll
            for (int c = 0; c < 4; c++) o[r][c] = 0.f;
#pragma unroll 4
        for (int kk = 0; kk < 64; kk++) {
            float a0 = sLb2[(ty * 4 + 0) * 68 + kk];
            float a1 = sLb2[(ty * 4 + 1) * 68 + kk];
            float a2 = sLb2[(ty * 4 + 2) * 68 + kk];
            float a3 = sLb2[(ty * 4 + 3) * 68 + kk];
            float4 b = *(const float4*)&sM[kk * 68 + tx * 4];
            o[0][0] -= a0 * b.x; o[0][1] -= a0 * b.y; o[0][2] -= a0 * b.z; o[0][3] -= a0 * b.w;
            o[1][0] -= a1 * b.x; o[1][1] -= a1 * b.y; o[1][2] -= a1 * b.z; o[1][3] -= a1 * b.w;
            o[2][0] -= a2 * b.x; o[2][1] -= a2 * b.y; o[2][2] -= a2 * b.z; o[2][3] -= a2 * b.w;
            o[3][0] -= a3 * b.x; o[3][1] -= a3 * b.y; o[3][2] -= a3 * b.z; o[3][3] -= a3 * b.w;
        }
        __syncthreads();
#pragma unroll
        for (int r = 0; r < 4; r++) {
            uint2 hi, lo;
            cvt_split(make_float4(o[r][0], o[r][1], o[r][2], o[r][3]), hi, lo);
            size_t goff = (size_t)(i * 64 + ty * 4 + r) * DD + j * 64 + tx * 4;
            *(uint2*)&VH[goff] = hi;
            *(uint2*)&VL[goff] = lo;
            if (i < 3) *(float4*)&sV[(i - j) * 4352 + (ty * 4 + r) * 68 + tx * 4] =
                make_float4(o[r][0], o[r][1], o[r][2], o[r][3]);
        }
        __syncthreads();
    }
}

// ---------------------------------------------------------------------------
// Kernel 3c: w[s][d] = sum_k Linv[s][d][k] * mu[s][k]  (from bf16 planes)
// ---------------------------------------------------------------------------
__global__ __launch_bounds__(256) void wvec_kernel(const float* __restrict__ mu) {
    __shared__ float smu[DD];
    const int s = blockIdx.x, tid = threadIdx.x, wid = tid >> 5, lane = tid & 31;
    smu[tid] = mu[(size_t)s * DD + tid];
    __syncthreads();
    const __nv_bfloat162* H = (const __nv_bfloat162*)(d_LinvH + (size_t)s * DD * DD);
    const __nv_bfloat162* Lp = (const __nv_bfloat162*)(d_LinvL + (size_t)s * DD * DD);
    for (int row = wid * 32; row < (wid + 1) * 32; row++) {
        float acc = 0.f;
#pragma unroll
        for (int q = 0; q < 4; q++) {
            int k2 = lane + 32 * q;
            __nv_bfloat162 hv = H[(size_t)row * 128 + k2];
            __nv_bfloat162 lv = Lp[(size_t)row * 128 + k2];
            acc += (__bfloat162float(hv.x) + __bfloat162float(lv.x)) * smu[2 * k2]
                 + (__bfloat162float(hv.y) + __bfloat162float(lv.y)) * smu[2 * k2 + 1];
        }
#pragma unroll
        for (int o = 16; o > 0; o >>= 1) acc += __shfl_xor_sync(0xFFFFFFFF, acc, o);
        if (lane == 0) d_w[(size_t)s * DD + row] = acc;
    }
}

// ---------------------------------------------------------------------------
// Kernel 4a: out[b][s] = -0.5*(D*log2pi + logdet[s])
// ---------------------------------------------------------------------------
__global__ __launch_bounds__(256) void init_out_kernel(float* __restrict__ out) {
    const float log2pi = 1.8378770664093453f;
    int b = blockIdx.x, s = threadIdx.x;
    out[(size_t)b * SS + s] = -0.5f * ((float)DD * log2pi + d_logdet[s]);
}

// ---------------------------------------------------------------------------
// Kernel 4b: Z = Linv_half * x^T via cp.async double-buffered bf16-split MMA;
// maha += colsum((Z - w)^2). All operands pre-split bf16 (pure-copy staging).
// smem: 2 bufs x 4 planes x [128][72] bf16 = 147456 B, + w[128] + red[512] fl.
// ---------------------------------------------------------------------------
#define LDA 72
#define PLANE (128 * LDA)
#define BUFE (4 * PLANE)
__global__ __launch_bounds__(256) void mahaZ_kernel(float* __restrict__ out) {
    extern __shared__ __nv_bfloat16 smh[];
    const uint32_t sbase = smem_u32(smh);
    float* sW = (float*)(smh + 2 * BUFE);       // 128 floats
    float* sRed = sW + 128;                      // 512 floats
    const int tid = threadIdx.x, wid = tid >> 5, lane = tid & 31;
    const int wm = wid & 3, wn = wid >> 2;
    const int b0 = blockIdx.x * 128, h = blockIdx.y, s = blockIdx.z;
    const int nchunks = 2 * (h + 1);

    const __nv_bfloat16* AH = d_LinvH + ((size_t)s * DD + h * 128) * DD;
    const __nv_bfloat16* AL = d_LinvL + ((size_t)s * DD + h * 128) * DD;
    const __nv_bfloat16* BH = d_xH + (size_t)b0 * DD;
    const __nv_bfloat16* BL = d_xL + (size_t)b0 * DD;

    if (tid < 128) sW[tid] = d_w[(size_t)s * DD + h * 128 + tid];

    float acc[2][8][4];
#pragma unroll
    for (int i = 0; i < 2; i++)
#pragma unroll
        for (int j = 0; j < 8; j++)
#pragma unroll
            for (int r = 0; r < 4; r++) acc[i][j][r] = 0.f;

    const uint32_t aRow = wm * 32 + (lane & 15);
    const uint32_t aColOff = ((lane >> 4) << 3);
    const uint32_t bRow = wn * 64 + (lane & 7) + ((lane >> 4) << 3);
    const uint32_t bColOff = (((lane >> 3) & 1) << 3);

    // staging: 16 cp.async of 16B per thread per chunk (4 planes x 4 steps)
#define ISSUE_CHUNK(c, buf) do {                                              \
    const int _k0 = (c) * 64;                                                 \
    const uint32_t _bb = sbase + (uint32_t)(buf) * (BUFE * 2);                \
    _Pragma("unroll")                                                         \
    for (int st = 0; st < 4; st++) {                                          \
        int rem = tid + 256 * st;                                             \
        int row = rem >> 3, q8 = (rem & 7) << 3;                              \
        uint32_t doff = (uint32_t)(row * LDA + q8) * 2;                       \
        size_t goff = (size_t)row * DD + _k0 + q8;                            \
        CP_ASYNC16(_bb + 0 * (PLANE * 2) + doff, AH + goff);                  \
        CP_ASYNC16(_bb + 1 * (PLANE * 2) + doff, AL + goff);                  \
        CP_ASYNC16(_bb + 2 * (PLANE * 2) + doff, BH + goff);                  \
        CP_ASYNC16(_bb + 3 * (PLANE * 2) + doff, BL + goff);                  \
    }                                                                         \
    asm volatile("cp.async.commit_group;");                                   \
} while (0)

    ISSUE_CHUNK(0, 0);
    for (int c = 0; c < nchunks; c++) {
        if (c + 1 < nchunks) {
            ISSUE_CHUNK(c + 1, (c + 1) & 1);
            asm volatile("cp.async.wait_group 1;");
        } else {
            asm volatile("cp.async.wait_group 0;");
        }
        __syncthreads();
        const uint32_t AHIb = sbase + (uint32_t)(c & 1) * (BUFE * 2);
        const uint32_t ALOb = AHIb + PLANE * 2;
        const uint32_t BHIb = AHIb + 2 * (PLANE * 2);
        const uint32_t BLOb = AHIb + 3 * (PLANE * 2);
#pragma unroll
        for (int ks = 0; ks < 4; ks++) {
            const uint32_t kc = ks * 16;
            uint32_t ahi[2][4], alo[2][4];
#pragma unroll
            for (int i = 0; i < 2; i++) {
                uint32_t ra = ((aRow + i * 16) * LDA + kc + aColOff) * 2;
                ldsm_x4(ahi[i][0], ahi[i][1], ahi[i][2], ahi[i][3], AHIb + ra);
                ldsm_x4(alo[i][0], alo[i][1], alo[i][2], alo[i][3], ALOb + ra);
            }
#pragma unroll
            for (int p = 0; p < 4; p++) {
                uint32_t bhi[4], blo[4];
                uint32_t rb = ((bRow + p * 16) * LDA + kc + bColOff) * 2;
                ldsm_x4(bhi[0], bhi[1], bhi[2], bhi[3], BHIb + rb);
                ldsm_x4(blo[0], blo[1], blo[2], blo[3], BLOb + rb);
#pragma unroll
                for (int i = 0; i < 2; i++) {
                    mma_bf16(acc[i][2 * p + 0], ahi[i], bhi[0], bhi[1]);
                    mma_bf16(acc[i][2 * p + 1], ahi[i], bhi[2], bhi[3]);
                    mma_bf16(acc[i][2 * p + 0], ahi[i], blo[0], blo[1]);
                    mma_bf16(acc[i][2 * p + 1], ahi[i], blo[2], blo[3]);
                    mma_bf16(acc[i][2 * p + 0], alo[i], bhi[0], bhi[1]);
                    mma_bf16(acc[i][2 * p + 1], alo[i], bhi[2], bhi[3]);
                }
            }
        }
        __syncthreads();
    }

    // epilogue: y = Z - w(row); column sums of y^2
    const int crow = lane >> 2;
    float wv[2][2];
#pragma unroll
    for (int i = 0; i < 2; i++) {
        wv[i][0] = sW[wm * 32 + i * 16 + crow];
        wv[i][1] = sW[wm * 32 + i * 16 + crow + 8];
    }
    float cs0[8], cs1[8];
#pragma unroll
    for (int j = 0; j < 8; j++) {
        float s0 = 0.f, s1 = 0.f;
#pragma unroll
        for (int i = 0; i < 2; i++) {
            float y0 = acc[i][j][0] - wv[i][0];
            float y1 = acc[i][j][1] - wv[i][0];
            float y2 = acc[i][j][2] - wv[i][1];
            float y3 = acc[i][j][3] - wv[i][1];
            s0 += y0 * y0 + y2 * y2;
            s1 += y1 * y1 + y3 * y3;
        }
#pragma unroll
        for (int o = 4; o <= 16; o <<= 1) {
            s0 += __shfl_xor_sync(0xFFFFFFFF, s0, o);
            s1 += __shfl_xor_sync(0xFFFFFFFF, s1, o);
        }
        cs0[j] = s0; cs1[j] = s1;
    }
    if (lane < 4) {
#pragma unroll
        for (int j = 0; j < 8; j++) {
            sRed[wid * 64 + j * 8 + 2 * lane + 0] = cs0[j];
            sRed[wid * 64 + j * 8 + 2 * lane + 1] = cs1[j];
        }
    }
    __syncthreads();
    if (tid < 128) {
        int nn = tid & 63, g = (tid >> 6) * 4;
        float m = sRed[(g + 0) * 64 + nn] + sRed[(g + 1) * 64 + nn]
                + sRed[(g + 2) * 64 + nn] + sRed[(g + 3) * 64 + nn];
        atomicAdd(&out[(size_t)(b0 + tid) * SS + s], -0.5f * m);
    }
}

// ---------------------------------------------------------------------------
extern "C" void kernel_launch(void* const* d_in, const int* in_sizes, int n_in,
                              void* d_out, int out_size) {
    const float* x  = (const float*)d_in[0];   // (1024, 256)
    const float* mu = (const float*)d_in[1];   // (256, 1, 256)
    const float* sg = (const float*)d_in[2];   // (256, 1, 256, 256)
    float* out = (float*)d_out;                // (1024, 256)

    cudaFuncSetAttribute(syrk_kernel,  cudaFuncAttributeMaxDynamicSharedMemorySize, 67584);
    cudaFuncSetAttribute(chol_kernel,  cudaFuncAttributeMaxDynamicSharedMemorySize, 87488);
    cudaFuncSetAttribute(linv_kernel,  cudaFuncAttributeMaxDynamicSharedMemorySize, 104448);
    cudaFuncSetAttribute(mahaZ_kernel, cudaFuncAttributeMaxDynamicSharedMemorySize, 150016);

    ridge_kernel<<<SS, 256>>>(sg);
    xcvt_kernel<<<256, 256>>>(x);
    syrk_kernel<<<dim3(3, SS), 256, 67584>>>(sg);
    chol_kernel<<<SS, 256, 87488>>>();
    linv_kernel<<<dim3(SS, 3), 256, 104448>>>();
    wvec_kernel<<<SS, 256>>>(mu);
    init_out_kernel<<<1024, 256>>>(out);
    mahaZ_kernel<<<dim3(8, 2, SS), 256, 150016>>>(out);
}